// round 8
// baseline (speedup 1.0000x reference)
#include <cuda_runtime.h>
#include <math.h>
#include <stdint.h>

#define BATCH   2048
#define CLASSES 128
#define FEAT    1024

#define BM 64
#define BN 128
#define KS 128                      // k-slice per block (2 chunks of 64)
#define KC 64                       // k-chunk resident in smem
#define SPLITK (FEAT / KS)          // 8
#define ASTR (BM + 4)               // 68
#define BSTR (BN + 4)               // 132
#define SMEM_FLOATS (KC * ASTR + KC * BSTR)

// split-K partials and Z partials
__device__ float g_part[SPLITK][BATCH][CLASSES];
__device__ float g_zpart[SPLITK][CLASSES];

// ---------------------------------------------------------------------------
__device__ __forceinline__ unsigned long long fma2(unsigned long long a,
                                                   unsigned long long b,
                                                   unsigned long long c) {
    unsigned long long d;
    asm("fma.rn.f32x2 %0, %1, %2, %3;" : "=l"(d) : "l"(a), "l"(b), "l"(c));
    return d;
}
__device__ __forceinline__ unsigned long long pack2(float lo, float hi) {
    unsigned long long r;
    asm("mov.b64 %0, {%1, %2};" : "=l"(r) : "f"(lo), "f"(hi));
    return r;
}
__device__ __forceinline__ void unpack2(unsigned long long v, float& lo, float& hi) {
    asm("mov.b64 {%0, %1}, %2;" : "=f"(lo), "=f"(hi) : "l"(v));
}

// ---------------------------------------------------------------------------
// Fused GEMM: part[z][b][c] = sum_{k in slice z} exp(x[b,k]) * exp(w[c,k])
// bx==0 blocks also emit zpart[z][c] = sum_k exp(w[c,k]).
// grid (32, 8). 256 threads. micro-tile 4m x 8n, n-paired f32x2 accumulators.
// ---------------------------------------------------------------------------
__global__ __launch_bounds__(256, 2)
void lse_gemm_kernel(const float* __restrict__ x, const float* __restrict__ w) {
    extern __shared__ float smem[];
    float (*As)[ASTR] = (float (*)[ASTR])smem;                 // [k][m]
    float (*Bs)[BSTR] = (float (*)[BSTR])(smem + KC * ASTR);   // [k][n]

    const int tid = threadIdx.x;
    const int bm = blockIdx.x * BM;
    const int kbase = blockIdx.y * KS;

    const int tx = tid & 15;        // n: tx*8
    const int ty = tid >> 4;        // m: ty*4

    unsigned long long acc[4][4];   // [m][n-pair]
    #pragma unroll
    for (int m = 0; m < 4; m++)
        #pragma unroll
        for (int p = 0; p < 4; p++) acc[m][p] = 0ULL;

    float zsum = 0.0f;

    // load mapping (per chunk): r = tid>>2, float4 cols q+4i (q=tid&3)
    const int lr = tid >> 2;        // 0..63
    const int lq = tid & 3;         // 0..3

    #pragma unroll
    for (int chunk = 0; chunk < 2; chunk++) {
        const int kc0 = kbase + chunk * KC;

        // ---- load + exp + transpose chunk into smem ----
        {
            const float* pa = x + (size_t)(bm + lr) * FEAT + kc0;
            #pragma unroll
            for (int i = 0; i < 4; i++) {
                const int k0 = (lq + 4 * i) * 4;
                float4 v = *(const float4*)(pa + k0);
                As[k0 + 0][lr] = __expf(v.x);
                As[k0 + 1][lr] = __expf(v.y);
                As[k0 + 2][lr] = __expf(v.z);
                As[k0 + 3][lr] = __expf(v.w);
            }
            #pragma unroll
            for (int half = 0; half < 2; half++) {
                const int r = lr + half * 64;
                const float* pb = w + (size_t)r * FEAT + kc0;
                #pragma unroll
                for (int i = 0; i < 4; i++) {
                    const int k0 = (lq + 4 * i) * 4;
                    float4 v = *(const float4*)(pb + k0);
                    Bs[k0 + 0][r] = __expf(v.x);
                    Bs[k0 + 1][r] = __expf(v.y);
                    Bs[k0 + 2][r] = __expf(v.z);
                    Bs[k0 + 3][r] = __expf(v.w);
                }
            }
        }
        __syncthreads();

        // ---- Z partial (B tile identical across bx; only bx==0 emits) ----
        if (blockIdx.x == 0 && tid < CLASSES) {
            #pragma unroll 16
            for (int k = 0; k < KC; k++) zsum += Bs[k][tid];
        }

        // ---- compute 64 k-steps ----
        #pragma unroll 8
        for (int k = 0; k < KC; k++) {
            float4 a4 = *(const float4*)(&As[k][ty * 4]);
            float4 b0 = *(const float4*)(&Bs[k][tx * 8]);
            float4 b1 = *(const float4*)(&Bs[k][tx * 8 + 4]);
            unsigned long long bp0 = pack2(b0.x, b0.y);
            unsigned long long bp1 = pack2(b0.z, b0.w);
            unsigned long long bp2 = pack2(b1.x, b1.y);
            unsigned long long bp3 = pack2(b1.z, b1.w);
            float am[4] = {a4.x, a4.y, a4.z, a4.w};
            #pragma unroll
            for (int m = 0; m < 4; m++) {
                unsigned long long ad = pack2(am[m], am[m]);
                acc[m][0] = fma2(ad, bp0, acc[m][0]);
                acc[m][1] = fma2(ad, bp1, acc[m][1]);
                acc[m][2] = fma2(ad, bp2, acc[m][2]);
                acc[m][3] = fma2(ad, bp3, acc[m][3]);
            }
        }
        if (chunk == 0) __syncthreads();   // protect smem before reload
    }

    if (blockIdx.x == 0 && tid < CLASSES)
        g_zpart[blockIdx.y][tid] = zsum;

    // ---- epilogue: 4 rows x 8 cols partials ----
    float* dst = &g_part[blockIdx.y][0][0];
    #pragma unroll
    for (int m = 0; m < 4; m++) {
        const size_t row = (size_t)(bm + ty * 4 + m) * CLASSES;
        float4 o0, o1;
        unpack2(acc[m][0], o0.x, o0.y);
        unpack2(acc[m][1], o0.z, o0.w);
        unpack2(acc[m][2], o1.x, o1.y);
        unpack2(acc[m][3], o1.z, o1.w);
        *(float4*)(&dst[row + tx * 8])     = o0;
        *(float4*)(&dst[row + tx * 8 + 4]) = o1;
    }
}

// ---------------------------------------------------------------------------
// Reduce: out[b,c] = log( (sum_z part[z][b][c]) / Z[c] )
// ---------------------------------------------------------------------------
__global__ __launch_bounds__(256)
void reduce_log_kernel(float* __restrict__ out) {
    __shared__ float rZ[CLASSES];
    const int tid = threadIdx.x;

    if (tid < CLASSES) {
        float s = 0.0f;
        #pragma unroll
        for (int z = 0; z < SPLITK; z++) s += g_zpart[z][tid];
        rZ[tid] = 1.0f / s;
    }
    __syncthreads();

    const int idx4 = blockIdx.x * 256 + tid;          // 0 .. 65535
    const float4* p = (const float4*)(&g_part[0][0][0]) + idx4;
    float4 s = p[0];
    #pragma unroll
    for (int z = 1; z < SPLITK; z++) {
        float4 v = p[(size_t)z * (BATCH * CLASSES / 4)];
        s.x += v.x; s.y += v.y; s.z += v.z; s.w += v.w;
    }
    const int c0 = (idx4 * 4) & (CLASSES - 1);
    float4 o;
    o.x = __logf(s.x * rZ[c0 + 0]);
    o.y = __logf(s.y * rZ[c0 + 1]);
    o.z = __logf(s.z * rZ[c0 + 2]);
    o.w = __logf(s.w * rZ[c0 + 3]);
    ((float4*)out)[idx4] = o;
}

// ---------------------------------------------------------------------------
extern "C" void kernel_launch(void* const* d_in, const int* in_sizes, int n_in,
                              void* d_out, int out_size) {
    const float* x = (const float*)d_in[0];
    const float* w = (const float*)d_in[1];
    if (in_sizes[0] == CLASSES * FEAT && in_sizes[1] == BATCH * FEAT) {
        w = (const float*)d_in[0];
        x = (const float*)d_in[1];
    }
    float* out = (float*)d_out;

    const int smem_bytes = SMEM_FLOATS * 4;
    cudaFuncSetAttribute(lse_gemm_kernel,
                         cudaFuncAttributeMaxDynamicSharedMemorySize, smem_bytes);

    dim3 grid(BATCH / BM, SPLITK);
    lse_gemm_kernel<<<grid, 256, smem_bytes>>>(x, w);
    reduce_log_kernel<<<(BATCH * CLASSES) / 4 / 256, 256>>>(out);
}

// round 9
// speedup vs baseline: 1.3087x; 1.3087x over previous
#include <cuda_runtime.h>
#include <math.h>
#include <stdint.h>

#define BATCH   2048
#define CLASSES 128
#define FEAT    1024

#define BM 128
#define BN 128
#define KS 128                      // k per block: 2 chunks of 64
#define KC 64                       // k-chunk resident in smem
#define SPLITK (FEAT / KS)          // 8
#define SROW 132                    // padded row
#define SMEM_BYTES (2 * KC * SROW * 4)

// split-K partials and Z partials
__device__ float g_part[SPLITK][BATCH][CLASSES];
__device__ float g_zpart[SPLITK][CLASSES];

// ---------------------------------------------------------------------------
__device__ __forceinline__ unsigned long long fma2(unsigned long long a,
                                                   unsigned long long b,
                                                   unsigned long long c) {
    unsigned long long d;
    asm("fma.rn.f32x2 %0, %1, %2, %3;" : "=l"(d) : "l"(a), "l"(b), "l"(c));
    return d;
}
__device__ __forceinline__ unsigned long long pack2(float lo, float hi) {
    unsigned long long r;
    asm("mov.b64 %0, {%1, %2};" : "=l"(r) : "f"(lo), "f"(hi));
    return r;
}
__device__ __forceinline__ void unpack2(unsigned long long v, float& lo, float& hi) {
    asm("mov.b64 {%0, %1}, %2;" : "=f"(lo), "=f"(hi) : "l"(v));
}

// ---------------------------------------------------------------------------
// Fused GEMM: part[z][b][c] = sum_{k in slice z} exp(x[b,k]) * exp(w[c,k])
// R6's proven inner loop (8x8 micro-tile, f32x2), now with KS=128 per block
// as two 64-k chunks reusing one smem buffer -> SPLITK=8, half the scratch.
// grid (16, 8), 256 threads.
// ---------------------------------------------------------------------------
__global__ __launch_bounds__(256, 2)
void lse_gemm_kernel(const float* __restrict__ x, const float* __restrict__ w) {
    extern __shared__ float smem[];
    float (*As)[SROW] = (float (*)[SROW])smem;               // [k][m], exp(x)
    float (*Bs)[SROW] = (float (*)[SROW])(smem + KC * SROW); // [k][n], exp(w)

    const int tid = threadIdx.x;
    const int bm = blockIdx.x * BM;
    const int kbase = blockIdx.y * KS;

    const int m0 = (tid >> 4) * 8;
    const int n0 = (tid & 15) * 8;

    unsigned long long acc[8][4];
    #pragma unroll
    for (int m = 0; m < 8; m++)
        #pragma unroll
        for (int p = 0; p < 4; p++) acc[m][p] = 0ULL;

    float zsum = 0.0f;

    const int r0 = tid >> 2;   // 0..63
    const int qb = tid & 3;    // 0..3

    #pragma unroll
    for (int chunk = 0; chunk < 2; chunk++) {
        const int kc0 = kbase + chunk * KC;

        // ---- load + exp + transpose this 64-k chunk ----
        {
            const float* ax = x + (size_t)(bm + r0) * FEAT + kc0;
            const float* bw = w + (size_t)r0 * FEAT + kc0;
            #pragma unroll
            for (int half = 0; half < 2; half++) {
                const int r = r0 + half * 64;
                const float* pa = ax + (size_t)half * 64 * FEAT;
                const float* pb = bw + (size_t)half * 64 * FEAT;
                #pragma unroll
                for (int i = 0; i < 4; i++) {
                    const int k0 = (qb + 4 * i) * 4;
                    float4 va = *(const float4*)(pa + k0);
                    As[k0 + 0][r] = __expf(va.x);
                    As[k0 + 1][r] = __expf(va.y);
                    As[k0 + 2][r] = __expf(va.z);
                    As[k0 + 3][r] = __expf(va.w);
                    float4 vb = *(const float4*)(pb + k0);
                    Bs[k0 + 0][r] = __expf(vb.x);
                    Bs[k0 + 1][r] = __expf(vb.y);
                    Bs[k0 + 2][r] = __expf(vb.z);
                    Bs[k0 + 3][r] = __expf(vb.w);
                }
            }
        }
        __syncthreads();

        // ---- Z partial (B tile identical across bx; only bx==0 emits) ----
        if (blockIdx.x == 0 && tid < CLASSES) {
            #pragma unroll 16
            for (int k = 0; k < KC; k++) zsum += Bs[k][tid];
        }

        // ---- compute 64 k-steps: 8x8 per thread ----
        #pragma unroll 8
        for (int k = 0; k < KC; k++) {
            float4 a0 = *(const float4*)(&As[k][m0]);
            float4 a1 = *(const float4*)(&As[k][m0 + 4]);
            float4 b0 = *(const float4*)(&Bs[k][n0]);
            float4 b1 = *(const float4*)(&Bs[k][n0 + 4]);
            unsigned long long bp0 = pack2(b0.x, b0.y);
            unsigned long long bp1 = pack2(b0.z, b0.w);
            unsigned long long bp2 = pack2(b1.x, b1.y);
            unsigned long long bp3 = pack2(b1.z, b1.w);
            float am[8] = {a0.x, a0.y, a0.z, a0.w, a1.x, a1.y, a1.z, a1.w};
            #pragma unroll
            for (int m = 0; m < 8; m++) {
                unsigned long long ad = pack2(am[m], am[m]);
                acc[m][0] = fma2(ad, bp0, acc[m][0]);
                acc[m][1] = fma2(ad, bp1, acc[m][1]);
                acc[m][2] = fma2(ad, bp2, acc[m][2]);
                acc[m][3] = fma2(ad, bp3, acc[m][3]);
            }
        }
        if (chunk == 0) __syncthreads();   // protect smem before reload
    }

    if (blockIdx.x == 0 && tid < CLASSES)
        g_zpart[blockIdx.y][tid] = zsum;

    // ---- epilogue: store 8x8 partials ----
    float* dst = &g_part[blockIdx.y][0][0];
    #pragma unroll
    for (int m = 0; m < 8; m++) {
        const size_t row = (size_t)(bm + m0 + m) * CLASSES;
        float4 o0, o1;
        unpack2(acc[m][0], o0.x, o0.y);
        unpack2(acc[m][1], o0.z, o0.w);
        unpack2(acc[m][2], o1.x, o1.y);
        unpack2(acc[m][3], o1.z, o1.w);
        *(float4*)(&dst[row + n0])     = o0;
        *(float4*)(&dst[row + n0 + 4]) = o1;
    }
}

// ---------------------------------------------------------------------------
// Reduce: out[b,c] = log( (sum_z part[z][b][c]) / Z[c] )
// ---------------------------------------------------------------------------
__global__ __launch_bounds__(256)
void reduce_log_kernel(float* __restrict__ out) {
    __shared__ float rZ[CLASSES];
    const int tid = threadIdx.x;

    if (tid < CLASSES) {
        float s = 0.0f;
        #pragma unroll
        for (int z = 0; z < SPLITK; z++) s += g_zpart[z][tid];
        rZ[tid] = 1.0f / s;
    }
    __syncthreads();

    const int idx4 = blockIdx.x * 256 + tid;          // 0 .. 65535
    const float4* p = (const float4*)(&g_part[0][0][0]) + idx4;
    float4 s = p[0];
    #pragma unroll
    for (int z = 1; z < SPLITK; z++) {
        float4 v = p[(size_t)z * (BATCH * CLASSES / 4)];
        s.x += v.x; s.y += v.y; s.z += v.z; s.w += v.w;
    }
    const int c0 = (idx4 * 4) & (CLASSES - 1);
    float4 o;
    o.x = __logf(s.x * rZ[c0 + 0]);
    o.y = __logf(s.y * rZ[c0 + 1]);
    o.z = __logf(s.z * rZ[c0 + 2]);
    o.w = __logf(s.w * rZ[c0 + 3]);
    ((float4*)out)[idx4] = o;
}

// ---------------------------------------------------------------------------
extern "C" void kernel_launch(void* const* d_in, const int* in_sizes, int n_in,
                              void* d_out, int out_size) {
    const float* x = (const float*)d_in[0];
    const float* w = (const float*)d_in[1];
    if (in_sizes[0] == CLASSES * FEAT && in_sizes[1] == BATCH * FEAT) {
        w = (const float*)d_in[0];
        x = (const float*)d_in[1];
    }
    float* out = (float*)d_out;

    cudaFuncSetAttribute(lse_gemm_kernel,
                         cudaFuncAttributeMaxDynamicSharedMemorySize, SMEM_BYTES);

    dim3 grid(BATCH / BM, SPLITK);
    lse_gemm_kernel<<<grid, 256, SMEM_BYTES>>>(x, w);
    reduce_log_kernel<<<(BATCH * CLASSES) / 4 / 256, 256>>>(out);
}

// round 11
// speedup vs baseline: 1.3138x; 1.0039x over previous
#include <cuda_runtime.h>
#include <math.h>
#include <stdint.h>

#define BATCH   2048
#define CLASSES 128
#define FEAT    1024

#define BM 128
#define BN 128
#define KS 128                      // k per block: 2 chunks of 64
#define KC 64                       // k-chunk resident in smem
#define SPLITK (FEAT / KS)          // 8
#define SROW 132                    // padded row
#define SMEM_BYTES (2 * KC * SROW * 4)

// split-K partials and Z partials
__device__ float g_part[SPLITK][BATCH][CLASSES];
__device__ float g_zpart[SPLITK][CLASSES];

// ---------------------------------------------------------------------------
__device__ __forceinline__ unsigned long long fma2(unsigned long long a,
                                                   unsigned long long b,
                                                   unsigned long long c) {
    unsigned long long d;
    asm("fma.rn.f32x2 %0, %1, %2, %3;" : "=l"(d) : "l"(a), "l"(b), "l"(c));
    return d;
}
__device__ __forceinline__ unsigned long long pack2(float lo, float hi) {
    unsigned long long r;
    asm("mov.b64 %0, {%1, %2};" : "=l"(r) : "f"(lo), "f"(hi));
    return r;
}
__device__ __forceinline__ void unpack2(unsigned long long v, float& lo, float& hi) {
    asm("mov.b64 {%0, %1}, %2;" : "=f"(lo), "=f"(hi) : "l"(v));
}

// ---------------------------------------------------------------------------
// Fused GEMM: part[z][b][c] = sum_{k in slice z} exp(x[b,k]) * exp(w[c,k])
// 8x8 micro-tile, f32x2 FMA, KS=128 as two 64-k chunks, register-prefetched.
// grid (16, 8), 256 threads, uncapped registers.
// ---------------------------------------------------------------------------
__global__ __launch_bounds__(256)
void lse_gemm_kernel(const float* __restrict__ x, const float* __restrict__ w) {
    extern __shared__ float smem[];
    float (*As)[SROW] = (float (*)[SROW])smem;               // [k][m], exp(x)
    float (*Bs)[SROW] = (float (*)[SROW])(smem + KC * SROW); // [k][n], exp(w)

    const int tid = threadIdx.x;
    const int bm = blockIdx.x * BM;
    const int kbase = blockIdx.y * KS;

    const int m0 = (tid >> 4) * 8;
    const int n0 = (tid & 15) * 8;

    unsigned long long acc[8][4];
    #pragma unroll
    for (int m = 0; m < 8; m++)
        #pragma unroll
        for (int p = 0; p < 4; p++) acc[m][p] = 0ULL;

    float zsum = 0.0f;

    const int r0 = tid >> 2;   // 0..63
    const int qb = tid & 3;    // 0..3

    const float* ax = x + (size_t)(bm + r0) * FEAT + kbase;
    const float* bw = w + (size_t)r0 * FEAT + kbase;

    // ---- chunk 0: load + exp + transpose into smem (BOTH halves, A and B) --
    #pragma unroll
    for (int half = 0; half < 2; half++) {
        const int r = r0 + half * 64;
        const float* pa = ax + (size_t)half * 64 * FEAT;
        const float* pb = bw + (size_t)half * 64 * FEAT;
        #pragma unroll
        for (int i = 0; i < 4; i++) {
            const int k0 = (qb + 4 * i) * 4;
            float4 va = *(const float4*)(pa + k0);
            As[k0 + 0][r] = __expf(va.x);
            As[k0 + 1][r] = __expf(va.y);
            As[k0 + 2][r] = __expf(va.z);
            As[k0 + 3][r] = __expf(va.w);
            float4 vb = *(const float4*)(pb + k0);
            Bs[k0 + 0][r] = __expf(vb.x);
            Bs[k0 + 1][r] = __expf(vb.y);
            Bs[k0 + 2][r] = __expf(vb.z);
            Bs[k0 + 3][r] = __expf(vb.w);
        }
    }
    __syncthreads();

    // ---- prefetch chunk 1 into registers: 16 x LDG.128 ----
    float4 pfa[2][4], pfb[2][4];
    #pragma unroll
    for (int half = 0; half < 2; half++) {
        const float* pa = ax + (size_t)half * 64 * FEAT + KC;
        const float* pb = bw + (size_t)half * 64 * FEAT + KC;
        #pragma unroll
        for (int i = 0; i < 4; i++) {
            const int k0 = (qb + 4 * i) * 4;
            pfa[half][i] = *(const float4*)(pa + k0);
            pfb[half][i] = *(const float4*)(pb + k0);
        }
    }

    // ---- compute chunk 0 ----
    #pragma unroll 8
    for (int k = 0; k < KC; k++) {
        float4 a0 = *(const float4*)(&As[k][m0]);
        float4 a1 = *(const float4*)(&As[k][m0 + 4]);
        float4 b0 = *(const float4*)(&Bs[k][n0]);
        float4 b1 = *(const float4*)(&Bs[k][n0 + 4]);
        unsigned long long bp0 = pack2(b0.x, b0.y);
        unsigned long long bp1 = pack2(b0.z, b0.w);
        unsigned long long bp2 = pack2(b1.x, b1.y);
        unsigned long long bp3 = pack2(b1.z, b1.w);
        float am[8] = {a0.x, a0.y, a0.z, a0.w, a1.x, a1.y, a1.z, a1.w};
        #pragma unroll
        for (int m = 0; m < 8; m++) {
            unsigned long long ad = pack2(am[m], am[m]);
            acc[m][0] = fma2(ad, bp0, acc[m][0]);
            acc[m][1] = fma2(ad, bp1, acc[m][1]);
            acc[m][2] = fma2(ad, bp2, acc[m][2]);
            acc[m][3] = fma2(ad, bp3, acc[m][3]);
        }
    }

    // ---- Z partial chunk 0 (B tile identical across bx; only bx==0 emits) ----
    if (blockIdx.x == 0 && tid < CLASSES) {
        #pragma unroll 16
        for (int k = 0; k < KC; k++) zsum += Bs[k][tid];
    }
    __syncthreads();

    // ---- store chunk 1 (exp applied) into smem ----
    #pragma unroll
    for (int half = 0; half < 2; half++) {
        const int r = r0 + half * 64;
        #pragma unroll
        for (int i = 0; i < 4; i++) {
            const int k0 = (qb + 4 * i) * 4;
            As[k0 + 0][r] = __expf(pfa[half][i].x);
            As[k0 + 1][r] = __expf(pfa[half][i].y);
            As[k0 + 2][r] = __expf(pfa[half][i].z);
            As[k0 + 3][r] = __expf(pfa[half][i].w);
            Bs[k0 + 0][r] = __expf(pfb[half][i].x);
            Bs[k0 + 1][r] = __expf(pfb[half][i].y);
            Bs[k0 + 2][r] = __expf(pfb[half][i].z);
            Bs[k0 + 3][r] = __expf(pfb[half][i].w);
        }
    }
    __syncthreads();

    // ---- compute chunk 1 ----
    #pragma unroll 8
    for (int k = 0; k < KC; k++) {
        float4 a0 = *(const float4*)(&As[k][m0]);
        float4 a1 = *(const float4*)(&As[k][m0 + 4]);
        float4 b0 = *(const float4*)(&Bs[k][n0]);
        float4 b1 = *(const float4*)(&Bs[k][n0 + 4]);
        unsigned long long bp0 = pack2(b0.x, b0.y);
        unsigned long long bp1 = pack2(b0.z, b0.w);
        unsigned long long bp2 = pack2(b1.x, b1.y);
        unsigned long long bp3 = pack2(b1.z, b1.w);
        float am[8] = {a0.x, a0.y, a0.z, a0.w, a1.x, a1.y, a1.z, a1.w};
        #pragma unroll
        for (int m = 0; m < 8; m++) {
            unsigned long long ad = pack2(am[m], am[m]);
            acc[m][0] = fma2(ad, bp0, acc[m][0]);
            acc[m][1] = fma2(ad, bp1, acc[m][1]);
            acc[m][2] = fma2(ad, bp2, acc[m][2]);
            acc[m][3] = fma2(ad, bp3, acc[m][3]);
        }
    }

    if (blockIdx.x == 0 && tid < CLASSES) {
        #pragma unroll 16
        for (int k = 0; k < KC; k++) zsum += Bs[k][tid];
        g_zpart[blockIdx.y][tid] = zsum;
    }

    // ---- epilogue: store 8x8 partials ----
    float* dst = &g_part[blockIdx.y][0][0];
    #pragma unroll
    for (int m = 0; m < 8; m++) {
        const size_t row = (size_t)(bm + m0 + m) * CLASSES;
        float4 o0, o1;
        unpack2(acc[m][0], o0.x, o0.y);
        unpack2(acc[m][1], o0.z, o0.w);
        unpack2(acc[m][2], o1.x, o1.y);
        unpack2(acc[m][3], o1.z, o1.w);
        *(float4*)(&dst[row + n0])     = o0;
        *(float4*)(&dst[row + n0 + 4]) = o1;
    }
}

// ---------------------------------------------------------------------------
// Reduce: out[b,c] = log( (sum_z part[z][b][c]) / Z[c] )
// 512 blocks x 256 thr; two threads per output (4 z-slices each), smem combine.
// ---------------------------------------------------------------------------
__global__ __launch_bounds__(256)
void reduce_log_kernel(float* __restrict__ out) {
    __shared__ float rZ[CLASSES];
    __shared__ float4 partial[128];
    const int tid = threadIdx.x;
    const int half = tid >> 7;          // 0 or 1
    const int i = tid & 127;

    if (tid < CLASSES) {
        float s = 0.0f;
        #pragma unroll
        for (int z = 0; z < SPLITK; z++) s += g_zpart[z][tid];
        rZ[tid] = 1.0f / s;
    }

    const int idx4 = blockIdx.x * 128 + i;             // 0 .. 65535
    const float4* p = (const float4*)(&g_part[0][0][0]) + idx4
                      + (size_t)(half * 4) * (BATCH * CLASSES / 4);
    float4 s = p[0];
    #pragma unroll
    for (int z = 1; z < 4; z++) {
        float4 v = p[(size_t)z * (BATCH * CLASSES / 4)];
        s.x += v.x; s.y += v.y; s.z += v.z; s.w += v.w;
    }
    if (half == 1) partial[i] = s;
    __syncthreads();
    if (half == 0) {
        float4 v = partial[i];
        s.x += v.x; s.y += v.y; s.z += v.z; s.w += v.w;
        const int c0 = (idx4 * 4) & (CLASSES - 1);
        float4 o;
        o.x = __logf(s.x * rZ[c0 + 0]);
        o.y = __logf(s.y * rZ[c0 + 1]);
        o.z = __logf(s.z * rZ[c0 + 2]);
        o.w = __logf(s.w * rZ[c0 + 3]);
        ((float4*)out)[idx4] = o;
    }
}

// ---------------------------------------------------------------------------
extern "C" void kernel_launch(void* const* d_in, const int* in_sizes, int n_in,
                              void* d_out, int out_size) {
    const float* x = (const float*)d_in[0];
    const float* w = (const float*)d_in[1];
    if (in_sizes[0] == CLASSES * FEAT && in_sizes[1] == BATCH * FEAT) {
        w = (const float*)d_in[0];
        x = (const float*)d_in[1];
    }
    float* out = (float*)d_out;

    cudaFuncSetAttribute(lse_gemm_kernel,
                         cudaFuncAttributeMaxDynamicSharedMemorySize, SMEM_BYTES);

    dim3 grid(BATCH / BM, SPLITK);
    lse_gemm_kernel<<<grid, 256, SMEM_BYTES>>>(x, w);
    reduce_log_kernel<<<(BATCH * CLASSES) / 4 / 128, 256>>>(out);
}